// round 14
// baseline (speedup 1.0000x reference)
#include <cuda_runtime.h>
#include <cuda_bf16.h>
#include <cstdint>

#define NB 16384
#define HD 768

// ---------------- scratch ----------------
__device__ __nv_bfloat16 g_featbf[4 * NB * 768];
__device__ __nv_bfloat16 g_lo1[2 * NB * 768];
__device__ __nv_bfloat16 g_h2[2 * NB * 256];
__device__ __nv_bfloat16 g_l2[2 * NB * 256];
__device__ __nv_bfloat16 g_scrAbf[2 * NB * 768];     // cons1 (bf16) [s2]
__device__ __nv_bfloat16 g_scrAbf3[NB * 768];        // diff1 (bf16) [s1]
__device__ __nv_bfloat16 g_scrCbf[4 * NB * 256];     // disc1 (bf16) [main]
__device__ float g_scrD2[2 * NB * 64];               // info2 (fp32) [s1]
__device__ float g_logit[11 * NB];                   // imp 4NB | disc 4NB | cons 2NB | diff NB
__device__ float g_norm[2 * NB];
__device__ __nv_bfloat16 g_w_imp1[384 * 768];
__device__ __nv_bfloat16 g_w_disc1[256 * 768];
__device__ __nv_bfloat16 g_w_disc2[64 * 256];
__device__ __nv_bfloat16 g_w_cons1[768 * 1536];
__device__ __nv_bfloat16 g_w_cons2[384 * 768];
__device__ __nv_bfloat16 g_w_diff1[768 * 1536];
__device__ __nv_bfloat16 g_w_diff2[384 * 768];
__device__ __nv_bfloat16 g_wi1h[256 * 768], g_wi1l[256 * 768];
__device__ __nv_bfloat16 g_wi2h[64 * 256],  g_wi2l[64 * 256];

__device__ __forceinline__ float sigf(float x) { return 1.0f / (1.0f + expf(-x)); }
__device__ __forceinline__ float geluf(float x) { return 0.5f * x * (1.0f + erff(x * 0.70710678118654752f)); }

__device__ __forceinline__ uint32_t smem_u32(const void* p) {
    uint32_t a;
    asm("{ .reg .u64 t; cvta.to.shared.u64 t, %1; cvt.u32.u64 %0, t; }" : "=r"(a) : "l"(p));
    return a;
}
__device__ __forceinline__ void mma_bf(float* d, const uint32_t* a, uint32_t b0, uint32_t b1) {
    asm volatile(
        "mma.sync.aligned.m16n8k16.row.col.f32.bf16.bf16.f32 "
        "{%0,%1,%2,%3}, {%4,%5,%6,%7}, {%8,%9}, {%0,%1,%2,%3};"
        : "+f"(d[0]), "+f"(d[1]), "+f"(d[2]), "+f"(d[3])
        : "r"(a[0]), "r"(a[1]), "r"(a[2]), "r"(a[3]), "r"(b0), "r"(b1));
}
#define LDSM4(r, addr) \
    asm volatile("ldmatrix.sync.aligned.m8n8.x4.shared.b16 {%0,%1,%2,%3}, [%4];" \
        : "=r"((r)[0]), "=r"((r)[1]), "=r"((r)[2]), "=r"((r)[3]) : "r"(addr))
#define CP_ASYNC16(dst, src) \
    asm volatile("cp.async.cg.shared.global [%0], [%1], 16;" :: "r"(dst), "l"(src))
#define CP_COMMIT() asm volatile("cp.async.commit_group;" ::: "memory")

struct APtrsB { const __nv_bfloat16* p[4]; };

// ================= bf16 GEMM: BM=128, BK=64, 3-stage, occ 2, two-region =================
// Per-region epilogue mode: 0 = fp32 store, 1 = bf16 store, 2 = head-fused.
template<int BN, int M0, int M1>
__global__ void __launch_bounds__(256, 2) gemm_bf16(
    APtrsB A, int Khalf, int Ktot,
    const __nv_bfloat16* __restrict__ Wt0, const __nv_bfloat16* __restrict__ Wt1,
    int N0, int N1, const float* __restrict__ b0, const float* __restrict__ b1,
    void* __restrict__ C0v, void* __restrict__ C1v,
    const float* __restrict__ w0, const float* __restrict__ w1, int act)
{
    constexpr int AW = 72;
    constexpr int ABYTES = 128 * AW * 2;
    constexpr int BBYTES = BN * AW * 2;
    constexpr int STG = ABYTES + BBYTES;
    constexpr int NT = BN / 16;

    extern __shared__ char smem[];
    const int t = threadIdx.x, lane = t & 31, wid = t >> 5;
    const int batch = blockIdx.y >> 7;
    const int m0 = (blockIdx.y & 127) * 128;
    const int n0g = blockIdx.x * BN;
    const int wm = (wid & 3) * 32;
    const int wn = (wid >> 2) * (BN / 2);

    const bool r1 = (n0g >= N0);
    const __nv_bfloat16* Wt = r1 ? Wt1 : Wt0;
    const float* bias = r1 ? b1 : b0;
    const int N = r1 ? N1 : N0;
    const int n0 = n0g - (r1 ? N0 : 0);

    const __nv_bfloat16 *A1, *A2;
    if (Khalf < Ktot) { A1 = A.p[2 * batch]; A2 = A.p[2 * batch + 1]; }
    else              { A1 = A.p[batch];     A2 = A1; }

    const uint32_t sbase = smem_u32(smem);
    const uint32_t a_addr0 = sbase + (uint32_t)((wm + (lane & 15)) * (AW * 2) + (lane >> 4) * 16);
    const int grp = lane >> 3;
    const int b_r = (lane & 7) + ((grp >= 2) ? 8 : 0);
    const uint32_t b_addr0 = sbase + ABYTES + (uint32_t)((wn + b_r) * (AW * 2) + (grp & 1) * 16);

    float acc[2][NT][4];
#pragma unroll
    for (int i = 0; i < 2; i++)
#pragma unroll
        for (int j = 0; j < NT; j++)
#pragma unroll
            for (int q = 0; q < 4; q++) acc[i][j][q] = 0.0f;

    auto load_chunk = [&](int c) {
        const int stg = c % 3;
        int kk = c * 64;
        const __nv_bfloat16* Ab = A1;
        if (kk >= Khalf) { Ab = A2; kk -= Khalf; }
        uint32_t sA = sbase + stg * STG;
#pragma unroll
        for (int i = 0; i < 4; i++) {
            int idx = t + i * 256, r = idx >> 3, c8 = idx & 7;
            CP_ASYNC16(sA + (uint32_t)(r * (AW * 2) + c8 * 16),
                       Ab + (size_t)(m0 + r) * Khalf + kk + c8 * 8);
        }
        uint32_t sB = sA + ABYTES;
#pragma unroll
        for (int i = 0; i < BN / 32; i++) {
            int idx = t + i * 256, r = idx >> 3, c8 = idx & 7;
            CP_ASYNC16(sB + (uint32_t)(r * (AW * 2) + c8 * 16),
                       Wt + (size_t)(n0 + r) * Ktot + c * 64 + c8 * 8);
        }
        CP_COMMIT();
    };

    const int NC = Ktot >> 6;
    load_chunk(0);
    if (NC > 1) load_chunk(1);

    for (int c = 0; c < NC; c++) {
        if (c + 1 < NC) { asm volatile("cp.async.wait_group 1;" ::: "memory"); }
        else            { asm volatile("cp.async.wait_group 0;" ::: "memory"); }
        __syncthreads();
        if (c + 2 < NC) load_chunk(c + 2);

        const uint32_t aa = a_addr0 + (c % 3) * STG;
        const uint32_t bb = b_addr0 + (c % 3) * STG;
#pragma unroll
        for (int kk = 0; kk < 4; kk++) {
            uint32_t Af[2][4];
            LDSM4(Af[0], aa + kk * 32);
            LDSM4(Af[1], aa + 16 * (AW * 2) + kk * 32);
#pragma unroll
            for (int np = 0; np < NT / 2; np++) {
                uint32_t B4[4];
                LDSM4(B4, bb + np * 16 * (AW * 2) + kk * 32);
#pragma unroll
                for (int mt = 0; mt < 2; mt++) {
                    mma_bf(acc[mt][2 * np],     Af[mt], B4[0], B4[1]);
                    mma_bf(acc[mt][2 * np + 1], Af[mt], B4[2], B4[3]);
                }
            }
        }
    }

    const int mode = r1 ? M1 : M0;
    const float* wv = r1 ? w1 : w0;
    void* Cv = r1 ? C1v : C0v;
#pragma unroll
    for (int mt = 0; mt < 2; mt++) {
        int row = batch * NB + m0 + wm + mt * 16 + (lane >> 2);
        float p0 = 0.f, p1 = 0.f;
#pragma unroll
        for (int nt = 0; nt < NT; nt++) {
            int col = n0 + wn + nt * 8 + (lane & 3) * 2;
            float bv0 = __ldg(bias + col), bv1 = __ldg(bias + col + 1);
            float x0 = acc[mt][nt][0] + bv0, x1 = acc[mt][nt][1] + bv1;
            float x2 = acc[mt][nt][2] + bv0, x3 = acc[mt][nt][3] + bv1;
            if (act) { x0 = geluf(x0); x1 = geluf(x1); x2 = geluf(x2); x3 = geluf(x3); }
            if (mode == 2) {
                float wv0 = __ldg(wv + col), wv1 = __ldg(wv + col + 1);
                p0 += x0 * wv0 + x1 * wv1;
                p1 += x2 * wv0 + x3 * wv1;
            } else if (mode == 1) {
                __nv_bfloat16* C = (__nv_bfloat16*)Cv;
                *reinterpret_cast<__nv_bfloat162*>(C + (size_t)row * N + col) =
                    __floats2bfloat162_rn(x0, x1);
                *reinterpret_cast<__nv_bfloat162*>(C + (size_t)(row + 8) * N + col) =
                    __floats2bfloat162_rn(x2, x3);
            } else {
                float* C = (float*)Cv;
                *reinterpret_cast<float2*>(C + (size_t)row * N + col)       = make_float2(x0, x1);
                *reinterpret_cast<float2*>(C + (size_t)(row + 8) * N + col) = make_float2(x2, x3);
            }
        }
        if (mode == 2) {
            p0 += __shfl_xor_sync(0xffffffffu, p0, 1);
            p0 += __shfl_xor_sync(0xffffffffu, p0, 2);
            p1 += __shfl_xor_sync(0xffffffffu, p1, 1);
            p1 += __shfl_xor_sync(0xffffffffu, p1, 2);
            if ((lane & 3) == 0) {
                float* L = (float*)Cv;
                atomicAdd(&L[row], p0);
                atomicAdd(&L[row + 8], p1);
            }
        }
    }
}

// ================= bf16x3 precise GEMM (info path); OUTSPLIT writes bf16 hi/lo =================
template<int BN, bool OUTSPLIT>
__global__ void __launch_bounds__(256, 2) gemm_bf3(
    APtrsB Ah, APtrsB Al, int Ktot,
    const __nv_bfloat16* __restrict__ Wh, const __nv_bfloat16* __restrict__ Wl, int N,
    const float* __restrict__ bias, void* __restrict__ Cv, void* __restrict__ Clv, int act)
{
    constexpr int AW = 40;
    constexpr int ABYTES = 128 * AW * 2;
    constexpr int BBYTES = BN * AW * 2;
    constexpr int STG = 2 * ABYTES + 2 * BBYTES;
    constexpr int NT = BN / 16;

    extern __shared__ char smem[];
    const int t = threadIdx.x, lane = t & 31, wid = t >> 5;
    const int batch = blockIdx.y >> 7;
    const int m0 = (blockIdx.y & 127) * 128;
    const int n0 = blockIdx.x * BN;
    const int wm = (wid & 3) * 32;
    const int wn = (wid >> 2) * (BN / 2);

    const __nv_bfloat16* A1h = Ah.p[batch];
    const __nv_bfloat16* A1l = Al.p[batch];

    const uint32_t sbase = smem_u32(smem);
    const uint32_t a_addr0 = sbase + (uint32_t)((wm + (lane & 15)) * AW * 2 + (lane >> 4) * 16);
    const int grp = lane >> 3;
    const int b_r = (lane & 7) + ((grp >= 2) ? 8 : 0);
    const uint32_t b_addr0 = sbase + 2 * ABYTES + (uint32_t)((wn + b_r) * AW * 2 + (grp & 1) * 16);

    float acc[2][NT][4];
#pragma unroll
    for (int i = 0; i < 2; i++)
#pragma unroll
        for (int j = 0; j < NT; j++)
#pragma unroll
            for (int q = 0; q < 4; q++) acc[i][j][q] = 0.0f;

    auto load_chunk = [&](int c) {
        const int stg = c & 1;
        const int kk = c * 32;
        uint32_t base = sbase + stg * STG;
#pragma unroll
        for (int i = 0; i < 2; i++) {
            int idx = t + i * 256, r = idx >> 2, c8 = idx & 3;
            uint32_t off = (uint32_t)(r * AW * 2 + c8 * 16);
            size_t go = (size_t)(m0 + r) * Ktot + kk + c8 * 8;
            CP_ASYNC16(base + off,           A1h + go);
            CP_ASYNC16(base + ABYTES + off,  A1l + go);
        }
        uint32_t sB = base + 2 * ABYTES;
#pragma unroll
        for (int i = 0; i < BN / 64; i++) {
            int idx = t + i * 256, r = idx >> 2, c8 = idx & 3;
            uint32_t off = (uint32_t)(r * AW * 2 + c8 * 16);
            size_t go = (size_t)(n0 + r) * Ktot + kk + c8 * 8;
            CP_ASYNC16(sB + off,           Wh + go);
            CP_ASYNC16(sB + BBYTES + off,  Wl + go);
        }
        CP_COMMIT();
    };

    const int NC = Ktot >> 5;
    load_chunk(0);
    if (NC > 1) load_chunk(1);

    for (int c = 0; c < NC; c++) {
        if (c + 1 < NC) { asm volatile("cp.async.wait_group 1;" ::: "memory"); }
        else            { asm volatile("cp.async.wait_group 0;" ::: "memory"); }
        __syncthreads();

        const uint32_t aa = a_addr0 + (c & 1) * STG;
        const uint32_t bb = b_addr0 + (c & 1) * STG;
#pragma unroll
        for (int kk = 0; kk < 2; kk++) {
            uint32_t Ahf[2][4], Alf[2][4];
            LDSM4(Ahf[0], aa + kk * 32);
            LDSM4(Ahf[1], aa + 16 * AW * 2 + kk * 32);
            LDSM4(Alf[0], aa + ABYTES + kk * 32);
            LDSM4(Alf[1], aa + ABYTES + 16 * AW * 2 + kk * 32);
#pragma unroll
            for (int np = 0; np < NT / 2; np++) {
                uint32_t Bh4[4], Bl4[4];
                LDSM4(Bh4, bb + np * 16 * AW * 2 + kk * 32);
                LDSM4(Bl4, bb + BBYTES + np * 16 * AW * 2 + kk * 32);
#pragma unroll
                for (int mt = 0; mt < 2; mt++) {
                    mma_bf(acc[mt][2 * np],     Ahf[mt], Bh4[0], Bh4[1]);
                    mma_bf(acc[mt][2 * np],     Ahf[mt], Bl4[0], Bl4[1]);
                    mma_bf(acc[mt][2 * np],     Alf[mt], Bh4[0], Bh4[1]);
                    mma_bf(acc[mt][2 * np + 1], Ahf[mt], Bh4[2], Bh4[3]);
                    mma_bf(acc[mt][2 * np + 1], Ahf[mt], Bl4[2], Bl4[3]);
                    mma_bf(acc[mt][2 * np + 1], Alf[mt], Bh4[2], Bh4[3]);
                }
            }
        }
        __syncthreads();
        if (c + 2 < NC) load_chunk(c + 2);
    }

#pragma unroll
    for (int mt = 0; mt < 2; mt++) {
        int row = batch * NB + m0 + wm + mt * 16 + (lane >> 2);
#pragma unroll
        for (int nt = 0; nt < NT; nt++) {
            int col = n0 + wn + nt * 8 + (lane & 3) * 2;
            float bv0 = bias[col], bv1 = bias[col + 1];
            float x0 = acc[mt][nt][0] + bv0, x1 = acc[mt][nt][1] + bv1;
            float x2 = acc[mt][nt][2] + bv0, x3 = acc[mt][nt][3] + bv1;
            if (act) { x0 = geluf(x0); x1 = geluf(x1); x2 = geluf(x2); x3 = geluf(x3); }
            if (OUTSPLIT) {
                __nv_bfloat16* Ch = (__nv_bfloat16*)Cv;
                __nv_bfloat16* Cl = (__nv_bfloat16*)Clv;
                __nv_bfloat162 h0 = __floats2bfloat162_rn(x0, x1);
                __nv_bfloat162 h1 = __floats2bfloat162_rn(x2, x3);
                *reinterpret_cast<__nv_bfloat162*>(Ch + (size_t)row * N + col) = h0;
                *reinterpret_cast<__nv_bfloat162*>(Ch + (size_t)(row + 8) * N + col) = h1;
                *reinterpret_cast<__nv_bfloat162*>(Cl + (size_t)row * N + col) =
                    __floats2bfloat162_rn(x0 - __bfloat162float(h0.x), x1 - __bfloat162float(h0.y));
                *reinterpret_cast<__nv_bfloat162*>(Cl + (size_t)(row + 8) * N + col) =
                    __floats2bfloat162_rn(x2 - __bfloat162float(h1.x), x3 - __bfloat162float(h1.y));
            } else {
                float* C = (float*)Cv;
                *reinterpret_cast<float2*>(C + (size_t)row * N + col)       = make_float2(x0, x1);
                *reinterpret_cast<float2*>(C + (size_t)(row + 8) * N + col) = make_float2(x2, x3);
            }
        }
    }
}

// ---------- fused: rowstats + fp32->bf16 hi(/lo) conversion, one input pass ----------
__global__ void fused_stats_cvt_k(
    const float* __restrict__ f0, const float* __restrict__ f1,
    const float* __restrict__ f2, const float* __restrict__ f3,
    __nv_bfloat16* __restrict__ hi, __nv_bfloat16* __restrict__ lo,
    float* __restrict__ out)
{
    int gw = (blockIdx.x * blockDim.x + threadIdx.x) >> 5;
    int lane = threadIdx.x & 31;
    if (gw >= 4 * NB) return;
    int feat = gw >> 14;
    int m = gw & (NB - 1);
    const float* f = (feat == 0 ? f0 : feat == 1 ? f1 : feat == 2 ? f2 : f3) + (size_t)m * HD;
    __nv_bfloat16* hrow = hi + ((size_t)feat * NB + m) * HD;
    __nv_bfloat16* lrow = lo + ((size_t)feat * NB + m) * HD;

    double sum = 0.0, ssq = 0.0;
    int cnt = 0;
    for (int k = lane * 4; k < HD; k += 128) {
        float4 v = *reinterpret_cast<const float4*>(f + k);
        sum += (double)v.x + v.y + v.z + v.w;
        ssq += (double)v.x * v.x + (double)v.y * v.y + (double)v.z * v.z + (double)v.w * v.w;
        cnt += (fabsf(v.x) > 0.01f) + (fabsf(v.y) > 0.01f) + (fabsf(v.z) > 0.01f) + (fabsf(v.w) > 0.01f);
        __nv_bfloat162 h0 = __floats2bfloat162_rn(v.x, v.y);
        __nv_bfloat162 h1 = __floats2bfloat162_rn(v.z, v.w);
        reinterpret_cast<__nv_bfloat162*>(hrow + k)[0] = h0;
        reinterpret_cast<__nv_bfloat162*>(hrow + k)[1] = h1;
        if (feat < 2) {
            reinterpret_cast<__nv_bfloat162*>(lrow + k)[0] =
                __floats2bfloat162_rn(v.x - __bfloat162float(h0.x), v.y - __bfloat162float(h0.y));
            reinterpret_cast<__nv_bfloat162*>(lrow + k)[1] =
                __floats2bfloat162_rn(v.z - __bfloat162float(h1.x), v.w - __bfloat162float(h1.y));
        }
    }
#pragma unroll
    for (int o = 16; o; o >>= 1) {
        sum += __shfl_xor_sync(0xffffffffu, sum, o);
        ssq += __shfl_xor_sync(0xffffffffu, ssq, o);
        cnt += __shfl_xor_sync(0xffffffffu, cnt, o);
    }
    if (lane == 0) {
        float n = (float)sqrt(ssq);
        float nq = sigf((n - 1.0f) * 2.0f);
        float sp = cnt * (1.0f / 768.0f);
        double var = (ssq - sum * sum / 768.0) / 767.0;
        if (var < 0.0) var = 0.0;
        float sq = sigf((float)sqrt(var) * 10.0f - 1.0f);
        out[feat * NB + m] = (nq + sp + sq) * (1.0f / 3.0f);
        if (feat < 2) g_norm[feat * NB + m] = n;
    }
}

// ---------------- zero logits ----------------
__global__ void zero_k(float4* __restrict__ p, int n4) {
    int i = blockIdx.x * blockDim.x + threadIdx.x;
    if (i < n4) p[i] = make_float4(0.f, 0.f, 0.f, 0.f);
}

// ---------------- finisher: sigmoids for all heads + overall row ----------------
// logits: [imp 4NB][disc 4NB][cons 2NB][diff NB]
__global__ void finish_k(const float* __restrict__ L,
                         const float* __restrict__ b_imp, const float* __restrict__ b_disc,
                         const float* __restrict__ b_cons, const float* __restrict__ b_diff,
                         float* __restrict__ out)
{
    int i = blockIdx.x * blockDim.x + threadIdx.x;
    if (i >= NB) return;
    float bi = b_imp[0], bd = b_disc[0], bc = b_cons[0], bf = b_diff[0];
    float imp0 = sigf(L[i] + bi);
    float imp1 = sigf(L[NB + i] + bi);
    out[8 * NB + i]  = imp0;
    out[9 * NB + i]  = imp1;
    out[10 * NB + i] = sigf(L[2 * NB + i] + bi);
    out[11 * NB + i] = sigf(L[3 * NB + i] + bi);
    out[12 * NB + i] = sigf(L[4 * NB + i] + bd);
    out[13 * NB + i] = sigf(L[5 * NB + i] + bd);
    out[14 * NB + i] = sigf(L[6 * NB + i] + bd);
    out[15 * NB + i] = sigf(L[7 * NB + i] + bd);
    out[6 * NB + i]  = sigf(L[8 * NB + i] + bc);
    float cons_e     = sigf(L[9 * NB + i] + bc);
    out[7 * NB + i]  = cons_e;
    out[16 * NB + i] = sigf(L[10 * NB + i] + bf);
    float v = out[0 * NB + i] + out[1 * NB + i] + out[4 * NB + i] + out[5 * NB + i] +
              cons_e + 0.5f * (imp0 + imp1);
    out[17 * NB + i] = v * (1.0f / 6.0f);
}

// ---------------- combined transpose: 9 jobs ----------------
struct TJobs {
    const float* s[9];
    __nv_bfloat16* d[9];
    __nv_bfloat16* dl[9];
    int K[9], N[9], t0[9];
    int njobs;
};
__global__ void transpose_combo_k(TJobs J) {
    __shared__ float tile[32][33];
    int bx = blockIdx.x;
    int j = 0;
#pragma unroll
    for (int q = 1; q < 9; q++) if (q < J.njobs && bx >= J.t0[q]) j = q;
    int local = bx - J.t0[j];
    int tilesx = J.N[j] / 32;
    int txb = local % tilesx, tyb = local / tilesx;
    const float* s = J.s[j];
    int K = J.K[j], N = J.N[j];
    int n = txb * 32 + threadIdx.x;
    int k = tyb * 32 + threadIdx.y;
#pragma unroll
    for (int i = 0; i < 32; i += 8) tile[threadIdx.y + i][threadIdx.x] = s[(size_t)(k + i) * N + n];
    __syncthreads();
    int n2 = txb * 32 + threadIdx.y;
    int k2 = tyb * 32 + threadIdx.x;
    __nv_bfloat16* d = J.d[j];
    __nv_bfloat16* dl = J.dl[j];
    if (dl == nullptr) {
#pragma unroll
        for (int i = 0; i < 32; i += 8)
            d[(size_t)(n2 + i) * K + k2] = __float2bfloat16(tile[threadIdx.x][threadIdx.y + i]);
    } else {
#pragma unroll
        for (int i = 0; i < 32; i += 8) {
            float v = tile[threadIdx.x][threadIdx.y + i];
            __nv_bfloat16 h = __float2bfloat16(v);
            d[(size_t)(n2 + i) * K + k2] = h;
            dl[(size_t)(n2 + i) * K + k2] = __float2bfloat16(v - __bfloat162float(h));
        }
    }
}

// ---------------- info final (2*NB rows) ----------------
__global__ void info_final_k(const float* __restrict__ enc, float* __restrict__ outrow)
{
    int gw = (blockIdx.x * blockDim.x + threadIdx.x) >> 5;
    int lane = threadIdx.x & 31;
    if (gw >= 2 * NB) return;
    const float* e = enc + (size_t)gw * 64;
    float x0 = e[lane], x1 = e[lane + 32];
    int d0 = (int)rintf(sigf(x0) * 10.0f);
    int d1 = (int)rintf(sigf(x1) * 10.0f);
    float ent = 0.f;
#pragma unroll
    for (int b = 0; b < 11; b++) {
        int c = __popc(__ballot_sync(0xffffffffu, d0 == b)) +
                __popc(__ballot_sync(0xffffffffu, d1 == b));
        if (c > 0) {
            float p = c * (1.0f / 64.0f);
            ent -= p * logf(p + 1e-8f);
        }
    }
    if (lane == 0) {
        float eq = sigf(ent - 2.0f);
        float n = g_norm[gw];
        float cq = (n > 0.01f) ? (1.0f / 768.0f) : 0.0f;
        float t = n / fmaxf(n, 1e-12f);
        float dq = sigf(t * t - 0.5f);
        outrow[gw] = (eq + cq + dq) * (1.0f / 3.0f);
    }
}

// ---------------- host ----------------
template<int BN, int M0, int M1>
static void launch_bf2(cudaStream_t st, APtrsB A, int nb, int Khalf, int Ktot,
                       const __nv_bfloat16* Wt0, const __nv_bfloat16* Wt1,
                       int N0, int N1, const float* b0, const float* b1,
                       void* C0, void* C1, const float* w0, const float* w1, int act)
{
    int smemB = 3 * (128 + BN) * 72 * 2;
    cudaFuncSetAttribute(gemm_bf16<BN, M0, M1>,
                         cudaFuncAttributeMaxDynamicSharedMemorySize, smemB);
    dim3 g((N0 + N1) / BN, nb * 128);
    gemm_bf16<BN, M0, M1><<<g, 256, smemB, st>>>(
        A, Khalf, Ktot, Wt0, Wt1, N0, N1, b0, b1, C0, C1, w0, w1, act);
}
template<int BN, int M>
static void launch_bf(cudaStream_t st, APtrsB A, int nb, int Khalf, int Ktot,
                      const __nv_bfloat16* Wt, int N, const float* bias, void* C,
                      const float* w, int act)
{
    launch_bf2<BN, M, M>(st, A, nb, Khalf, Ktot, Wt, nullptr, N, 0, bias, nullptr,
                         C, nullptr, w, nullptr, act);
}
template<int BN, bool OUTSPLIT>
static void launch_bf3(cudaStream_t st, APtrsB Ah, APtrsB Al, int nb, int Ktot,
                       const __nv_bfloat16* Wh, const __nv_bfloat16* Wl, int N,
                       const float* bias, void* C, void* Cl, int act)
{
    int smemB = 2 * (2 * 128 * 40 * 2 + 2 * BN * 40 * 2);
    cudaFuncSetAttribute(gemm_bf3<BN, OUTSPLIT>, cudaFuncAttributeMaxDynamicSharedMemorySize, smemB);
    dim3 g(N / BN, nb * 128);
    gemm_bf3<BN, OUTSPLIT><<<g, 256, smemB, st>>>(Ah, Al, Ktot, Wh, Wl, N, bias, C, Cl, act);
}

extern "C" void kernel_launch(void* const* d_in, const int* in_sizes, int n_in,
                              void* d_out, int out_size)
{
    const float* img  = (const float*)d_in[0];
    const float* txt  = (const float*)d_in[1];
    const float* eimg = (const float*)d_in[2];
    const float* etxt = (const float*)d_in[3];
    const float* info_w1 = (const float*)d_in[5];
    const float* info_b1 = (const float*)d_in[6];
    const float* info_w2 = (const float*)d_in[7];
    const float* info_b2 = (const float*)d_in[8];
    const float* imp_w1  = (const float*)d_in[9];
    const float* imp_b1  = (const float*)d_in[10];
    const float* imp_w2  = (const float*)d_in[11];
    const float* imp_b2  = (const float*)d_in[12];
    const float* disc_w1 = (const float*)d_in[13];
    const float* disc_b1 = (const float*)d_in[14];
    const float* disc_w2 = (const float*)d_in[15];
    const float* disc_b2 = (const float*)d_in[16];
    const float* disc_w3 = (const float*)d_in[17];
    const float* disc_b3 = (const float*)d_in[18];
    const float* cons_w1 = (const float*)d_in[19];
    const float* cons_b1 = (const float*)d_in[20];
    const float* cons_w2 = (const float*)d_in[21];
    const float* cons_b2 = (const float*)d_in[22];
    const float* cons_w3 = (const float*)d_in[23];
    const float* cons_b3 = (const float*)d_in[24];
    const float* diff_w1 = (const float*)d_in[25];
    const float* diff_b1 = (const float*)d_in[26];
    const float* diff_w2 = (const float*)d_in[27];
    const float* diff_b2 = (const float*)d_in[28];
    const float* diff_w3 = (const float*)d_in[29];
    const float* diff_b3 = (const float*)d_in[30];

    float* out = (float*)d_out;

    __nv_bfloat16 *featbf, *lo1, *h2, *l2, *scrAbf, *scrAbf3, *scrCbf;
    __nv_bfloat16 *w_imp1, *w_disc1, *w_disc2, *w_cons1, *w_cons2, *w_diff1, *w_diff2;
    __nv_bfloat16 *wi1h, *wi1l, *wi2h, *wi2l;
    float *scrD2, *logit;
    cudaGetSymbolAddress((void**)&featbf, g_featbf);
    cudaGetSymbolAddress((void**)&lo1, g_lo1);
    cudaGetSymbolAddress((void**)&h2, g_h2);
    cudaGetSymbolAddress((void**)&l2, g_l2);
    cudaGetSymbolAddress((void**)&scrAbf, g_scrAbf);
    cudaGetSymbolAddress((void**)&scrAbf3, g_scrAbf3);
    cudaGetSymbolAddress((void**)&scrCbf, g_scrCbf);
    cudaGetSymbolAddress((void**)&scrD2, g_scrD2);
    cudaGetSymbolAddress((void**)&logit, g_logit);
    cudaGetSymbolAddress((void**)&w_imp1, g_w_imp1);
    cudaGetSymbolAddress((void**)&w_disc1, g_w_disc1);
    cudaGetSymbolAddress((void**)&w_disc2, g_w_disc2);
    cudaGetSymbolAddress((void**)&w_cons1, g_w_cons1);
    cudaGetSymbolAddress((void**)&w_cons2, g_w_cons2);
    cudaGetSymbolAddress((void**)&w_diff1, g_w_diff1);
    cudaGetSymbolAddress((void**)&w_diff2, g_w_diff2);
    cudaGetSymbolAddress((void**)&wi1h, g_wi1h);
    cudaGetSymbolAddress((void**)&wi1l, g_wi1l);
    cudaGetSymbolAddress((void**)&wi2h, g_wi2h);
    cudaGetSymbolAddress((void**)&wi2l, g_wi2l);

    float* logit_imp  = logit;
    float* logit_disc = logit + 4 * NB;
    float* logit_cons = logit + 8 * NB;
    float* logit_diff = logit + 10 * NB;

    const __nv_bfloat16* bimg  = featbf;
    const __nv_bfloat16* btxt  = featbf + (size_t)NB * 768;
    const __nv_bfloat16* beimg = featbf + (size_t)2 * NB * 768;
    const __nv_bfloat16* betxt = featbf + (size_t)3 * NB * 768;

    static cudaStream_t s1 = nullptr, s2 = nullptr;
    static cudaEvent_t e0 = nullptr, eF = nullptr, eW = nullptr, e1 = nullptr, e2 = nullptr;
    if (!s1) {
        cudaStreamCreateWithFlags(&s1, cudaStreamNonBlocking);
        cudaStreamCreateWithFlags(&s2, cudaStreamNonBlocking);
        cudaEventCreateWithFlags(&e0, cudaEventDisableTiming);
        cudaEventCreateWithFlags(&eF, cudaEventDisableTiming);
        cudaEventCreateWithFlags(&eW, cudaEventDisableTiming);
        cudaEventCreateWithFlags(&e1, cudaEventDisableTiming);
        cudaEventCreateWithFlags(&e2, cudaEventDisableTiming);
    }

    // fork
    cudaEventRecord(e0, 0);
    cudaStreamWaitEvent(s1, e0, 0);
    cudaStreamWaitEvent(s2, e0, 0);

    // s2: weight transposes + logit zero (weights only)
    {
        TJobs J;
        const float* srcs[9] = { imp_w1, disc_w1, disc_w2, cons_w1, cons_w2, diff_w1, diff_w2,
                                 info_w1, info_w2 };
        __nv_bfloat16* dsts[9] = { w_imp1, w_disc1, w_disc2, w_cons1, w_cons2, w_diff1, w_diff2,
                                   wi1h, wi2h };
        __nv_bfloat16* dls[9] = { nullptr, nullptr, nullptr, nullptr, nullptr, nullptr, nullptr,
                                  wi1l, wi2l };
        int Ks[9] = { 768, 768, 256, 1536, 768, 1536, 768, 768, 256 };
        int Ns[9] = { 384, 256, 64, 768, 384, 768, 384, 256, 64 };
        int tot = 0;
        for (int j = 0; j < 9; j++) {
            J.s[j] = srcs[j]; J.d[j] = dsts[j]; J.dl[j] = dls[j];
            J.K[j] = Ks[j]; J.N[j] = Ns[j];
            J.t0[j] = tot;
            tot += (Ks[j] / 32) * (Ns[j] / 32);
        }
        J.njobs = 9;
        dim3 b(32, 8);
        transpose_combo_k<<<tot, b, 0, s2>>>(J);
        zero_k<<<(11 * NB / 4 + 255) / 256, 256, 0, s2>>>((float4*)logit, 11 * NB / 4);
        cudaEventRecord(eW, s2);
    }

    // main: fused input pass (stats rows 0..3 + norms + bf16 hi/lo)
    fused_stats_cvt_k<<<(4 * NB) / 8, 256>>>(img, txt, eimg, etxt, featbf, lo1, out);
    cudaEventRecord(eF, 0);

    cudaStreamWaitEvent(0, eW, 0);
    cudaStreamWaitEvent(s1, eF, 0);
    cudaStreamWaitEvent(s1, eW, 0);
    cudaStreamWaitEvent(s2, eF, 0);

    // s1: information (rows 4,5) — bf16x3, then diff chain (row 16)
    {
        APtrsB ah = {{ bimg, btxt, nullptr, nullptr }};
        APtrsB al = {{ lo1, lo1 + (size_t)NB * 768, nullptr, nullptr }};
        launch_bf3<128, true>(s1, ah, al, 2, 768, wi1h, wi1l, 256, info_b1, h2, l2, 1);
        APtrsB ah2 = {{ h2, h2 + (size_t)NB * 256, nullptr, nullptr }};
        APtrsB al2 = {{ l2, l2 + (size_t)NB * 256, nullptr, nullptr }};
        launch_bf3<64, false>(s1, ah2, al2, 2, 256, wi2h, wi2l, 64, info_b2, scrD2, nullptr, 0);
        info_final_k<<<(2 * NB) / 8, 256, 0, s1>>>(scrD2, out + 4 * NB);

        APtrsB af = {{ beimg, betxt, nullptr, nullptr }};
        launch_bf<128, 1>(s1, af, 1, 768, 1536, w_diff1, 768, diff_b1, scrAbf3, nullptr, 1);
        APtrsB af2 = {{ scrAbf3, nullptr, nullptr, nullptr }};
        launch_bf<128, 2>(s1, af2, 1, 768, 768, w_diff2, 384, diff_b2, logit_diff, diff_w3, 1);
        cudaEventRecord(e1, s1);
    }

    // main: merged imp1(head)+disc1(bf16), then disc2(head)
    {
        APtrsB a = {{ bimg, btxt, beimg, betxt }};
        launch_bf2<128, 2, 1>(0, a, 4, 768, 768,
                              w_imp1, w_disc1, 384, 256, imp_b1, disc_b1,
                              logit_imp, scrCbf, imp_w2, nullptr, 1);
        // disc2: batch order img,eimg,txt,etxt -> rows 12..15
        APtrsB ad2 = {{ scrCbf, scrCbf + (size_t)2 * NB * 256, scrCbf + (size_t)NB * 256,
                        scrCbf + (size_t)3 * NB * 256 }};
        launch_bf<64, 2>(0, ad2, 4, 256, 256, w_disc2, 64, disc_b2, logit_disc, disc_w3, 1);
    }

    // s2: consistency (rows 6,7), head-fused layer 2
    {
        APtrsB a = {{ bimg, btxt, beimg, betxt }};
        launch_bf<128, 1>(s2, a, 2, 768, 1536, w_cons1, 768, cons_b1, scrAbf, nullptr, 1);
        APtrsB a2 = {{ scrAbf, scrAbf + (size_t)NB * 768, nullptr, nullptr }};
        launch_bf<128, 2>(s2, a2, 2, 768, 768, w_cons2, 384, cons_b2, logit_cons, cons_w3, 1);
        cudaEventRecord(e2, s2);
    }

    // join: all logits + info rows -> one finisher (heads + overall)
    cudaStreamWaitEvent(0, e1, 0);
    cudaStreamWaitEvent(0, e2, 0);
    finish_k<<<(NB + 255) / 256, 256>>>(logit, imp_b2, disc_b3, cons_b3, diff_b3, out);
}

// round 15
// speedup vs baseline: 1.0144x; 1.0144x over previous
#include <cuda_runtime.h>
#include <cuda_bf16.h>
#include <cstdint>

#define NB 16384
#define HD 768

// ---------------- scratch ----------------
__device__ __nv_bfloat16 g_featbf[4 * NB * 768];
__device__ __nv_bfloat16 g_lo1[2 * NB * 768];
__device__ __nv_bfloat16 g_h2[2 * NB * 256];
__device__ __nv_bfloat16 g_l2[2 * NB * 256];
__device__ __nv_bfloat16 g_scrAbf[2 * NB * 768];     // cons1 (bf16) [s2]
__device__ __nv_bfloat16 g_scrAbf3[NB * 768];        // diff1 (bf16) [main]
__device__ __nv_bfloat16 g_scrCbf[4 * NB * 256];     // disc1 (bf16) [main]
__device__ float g_scrD2[2 * NB * 64];               // info2 (fp32) [s1]
__device__ float g_logit[11 * NB];                   // imp 4NB | disc 4NB | cons 2NB | diff NB
__device__ float g_norm[2 * NB];
__device__ __nv_bfloat16 g_w_imp1[384 * 768];
__device__ __nv_bfloat16 g_w_disc1[256 * 768];
__device__ __nv_bfloat16 g_w_disc2[64 * 256];
__device__ __nv_bfloat16 g_w_cons1[768 * 1536];
__device__ __nv_bfloat16 g_w_cons2[384 * 768];
__device__ __nv_bfloat16 g_w_diff1[768 * 1536];
__device__ __nv_bfloat16 g_w_diff2[384 * 768];
__device__ __nv_bfloat16 g_wi1h[256 * 768], g_wi1l[256 * 768];
__device__ __nv_bfloat16 g_wi2h[64 * 256],  g_wi2l[64 * 256];

__device__ __forceinline__ float sigf(float x) { return 1.0f / (1.0f + expf(-x)); }
__device__ __forceinline__ float geluf(float x) { return 0.5f * x * (1.0f + erff(x * 0.70710678118654752f)); }

__device__ __forceinline__ uint32_t smem_u32(const void* p) {
    uint32_t a;
    asm("{ .reg .u64 t; cvta.to.shared.u64 t, %1; cvt.u32.u64 %0, t; }" : "=r"(a) : "l"(p));
    return a;
}
__device__ __forceinline__ void mma_bf(float* d, const uint32_t* a, uint32_t b0, uint32_t b1) {
    asm volatile(
        "mma.sync.aligned.m16n8k16.row.col.f32.bf16.bf16.f32 "
        "{%0,%1,%2,%3}, {%4,%5,%6,%7}, {%8,%9}, {%0,%1,%2,%3};"
        : "+f"(d[0]), "+f"(d[1]), "+f"(d[2]), "+f"(d[3])
        : "r"(a[0]), "r"(a[1]), "r"(a[2]), "r"(a[3]), "r"(b0), "r"(b1));
}
#define LDSM4(r, addr) \
    asm volatile("ldmatrix.sync.aligned.m8n8.x4.shared.b16 {%0,%1,%2,%3}, [%4];" \
        : "=r"((r)[0]), "=r"((r)[1]), "=r"((r)[2]), "=r"((r)[3]) : "r"(addr))
#define CP_ASYNC16(dst, src) \
    asm volatile("cp.async.cg.shared.global [%0], [%1], 16;" :: "r"(dst), "l"(src))
#define CP_COMMIT() asm volatile("cp.async.commit_group;" ::: "memory")

struct APtrsB { const __nv_bfloat16* p[4]; };

// ================= bf16 GEMM: BM=128, BK=64, 3-stage, occ 2, two-region =================
// Per-region epilogue mode: 0 = fp32 store, 1 = bf16 store, 2 = head-fused.
template<int BN, int M0, int M1>
__global__ void __launch_bounds__(256, 2) gemm_bf16(
    APtrsB A, int Khalf, int Ktot,
    const __nv_bfloat16* __restrict__ Wt0, const __nv_bfloat16* __restrict__ Wt1,
    int N0, int N1, const float* __restrict__ b0, const float* __restrict__ b1,
    void* __restrict__ C0v, void* __restrict__ C1v,
    const float* __restrict__ w0, const float* __restrict__ w1, int act)
{
    constexpr int AW = 72;
    constexpr int ABYTES = 128 * AW * 2;
    constexpr int BBYTES = BN * AW * 2;
    constexpr int STG = ABYTES + BBYTES;
    constexpr int NT = BN / 16;

    extern __shared__ char smem[];
    const int t = threadIdx.x, lane = t & 31, wid = t >> 5;
    const int batch = blockIdx.y >> 7;
    const int m0 = (blockIdx.y & 127) * 128;
    const int n0g = blockIdx.x * BN;
    const int wm = (wid & 3) * 32;
    const int wn = (wid >> 2) * (BN / 2);

    const bool r1 = (n0g >= N0);
    const __nv_bfloat16* Wt = r1 ? Wt1 : Wt0;
    const float* bias = r1 ? b1 : b0;
    const int N = r1 ? N1 : N0;
    const int n0 = n0g - (r1 ? N0 : 0);

    const __nv_bfloat16 *A1, *A2;
    if (Khalf < Ktot) { A1 = A.p[2 * batch]; A2 = A.p[2 * batch + 1]; }
    else              { A1 = A.p[batch];     A2 = A1; }

    const uint32_t sbase = smem_u32(smem);
    const uint32_t a_addr0 = sbase + (uint32_t)((wm + (lane & 15)) * (AW * 2) + (lane >> 4) * 16);
    const int grp = lane >> 3;
    const int b_r = (lane & 7) + ((grp >= 2) ? 8 : 0);
    const uint32_t b_addr0 = sbase + ABYTES + (uint32_t)((wn + b_r) * (AW * 2) + (grp & 1) * 16);

    float acc[2][NT][4];
#pragma unroll
    for (int i = 0; i < 2; i++)
#pragma unroll
        for (int j = 0; j < NT; j++)
#pragma unroll
            for (int q = 0; q < 4; q++) acc[i][j][q] = 0.0f;

    auto load_chunk = [&](int c) {
        const int stg = c % 3;
        int kk = c * 64;
        const __nv_bfloat16* Ab = A1;
        if (kk >= Khalf) { Ab = A2; kk -= Khalf; }
        uint32_t sA = sbase + stg * STG;
#pragma unroll
        for (int i = 0; i < 4; i++) {
            int idx = t + i * 256, r = idx >> 3, c8 = idx & 7;
            CP_ASYNC16(sA + (uint32_t)(r * (AW * 2) + c8 * 16),
                       Ab + (size_t)(m0 + r) * Khalf + kk + c8 * 8);
        }
        uint32_t sB = sA + ABYTES;
#pragma unroll
        for (int i = 0; i < BN / 32; i++) {
            int idx = t + i * 256, r = idx >> 3, c8 = idx & 7;
            CP_ASYNC16(sB + (uint32_t)(r * (AW * 2) + c8 * 16),
                       Wt + (size_t)(n0 + r) * Ktot + c * 64 + c8 * 8);
        }
        CP_COMMIT();
    };

    const int NC = Ktot >> 6;
    load_chunk(0);
    if (NC > 1) load_chunk(1);

    for (int c = 0; c < NC; c++) {
        if (c + 1 < NC) { asm volatile("cp.async.wait_group 1;" ::: "memory"); }
        else            { asm volatile("cp.async.wait_group 0;" ::: "memory"); }
        __syncthreads();
        if (c + 2 < NC) load_chunk(c + 2);

        const uint32_t aa = a_addr0 + (c % 3) * STG;
        const uint32_t bb = b_addr0 + (c % 3) * STG;
#pragma unroll
        for (int kk = 0; kk < 4; kk++) {
            uint32_t Af[2][4];
            LDSM4(Af[0], aa + kk * 32);
            LDSM4(Af[1], aa + 16 * (AW * 2) + kk * 32);
#pragma unroll
            for (int np = 0; np < NT / 2; np++) {
                uint32_t B4[4];
                LDSM4(B4, bb + np * 16 * (AW * 2) + kk * 32);
#pragma unroll
                for (int mt = 0; mt < 2; mt++) {
                    mma_bf(acc[mt][2 * np],     Af[mt], B4[0], B4[1]);
                    mma_bf(acc[mt][2 * np + 1], Af[mt], B4[2], B4[3]);
                }
            }
        }
    }

    const int mode = r1 ? M1 : M0;
    const float* wv = r1 ? w1 : w0;
    void* Cv = r1 ? C1v : C0v;
#pragma unroll
    for (int mt = 0; mt < 2; mt++) {
        int row = batch * NB + m0 + wm + mt * 16 + (lane >> 2);
        float p0 = 0.f, p1 = 0.f;
#pragma unroll
        for (int nt = 0; nt < NT; nt++) {
            int col = n0 + wn + nt * 8 + (lane & 3) * 2;
            float bv0 = __ldg(bias + col), bv1 = __ldg(bias + col + 1);
            float x0 = acc[mt][nt][0] + bv0, x1 = acc[mt][nt][1] + bv1;
            float x2 = acc[mt][nt][2] + bv0, x3 = acc[mt][nt][3] + bv1;
            if (act) { x0 = geluf(x0); x1 = geluf(x1); x2 = geluf(x2); x3 = geluf(x3); }
            if (mode == 2) {
                float wv0 = __ldg(wv + col), wv1 = __ldg(wv + col + 1);
                p0 += x0 * wv0 + x1 * wv1;
                p1 += x2 * wv0 + x3 * wv1;
            } else if (mode == 1) {
                __nv_bfloat16* C = (__nv_bfloat16*)Cv;
                *reinterpret_cast<__nv_bfloat162*>(C + (size_t)row * N + col) =
                    __floats2bfloat162_rn(x0, x1);
                *reinterpret_cast<__nv_bfloat162*>(C + (size_t)(row + 8) * N + col) =
                    __floats2bfloat162_rn(x2, x3);
            } else {
                float* C = (float*)Cv;
                *reinterpret_cast<float2*>(C + (size_t)row * N + col)       = make_float2(x0, x1);
                *reinterpret_cast<float2*>(C + (size_t)(row + 8) * N + col) = make_float2(x2, x3);
            }
        }
        if (mode == 2) {
            p0 += __shfl_xor_sync(0xffffffffu, p0, 1);
            p0 += __shfl_xor_sync(0xffffffffu, p0, 2);
            p1 += __shfl_xor_sync(0xffffffffu, p1, 1);
            p1 += __shfl_xor_sync(0xffffffffu, p1, 2);
            if ((lane & 3) == 0) {
                float* L = (float*)Cv;
                atomicAdd(&L[row], p0);
                atomicAdd(&L[row + 8], p1);
            }
        }
    }
}

// ================= bf16x3 precise GEMM (info path); OUTSPLIT writes bf16 hi/lo =================
template<int BN, bool OUTSPLIT>
__global__ void __launch_bounds__(256, 2) gemm_bf3(
    APtrsB Ah, APtrsB Al, int Ktot,
    const __nv_bfloat16* __restrict__ Wh, const __nv_bfloat16* __restrict__ Wl, int N,
    const float* __restrict__ bias, void* __restrict__ Cv, void* __restrict__ Clv, int act)
{
    constexpr int AW = 40;
    constexpr int ABYTES = 128 * AW * 2;
    constexpr int BBYTES = BN * AW * 2;
    constexpr int STG = 2 * ABYTES + 2 * BBYTES;
    constexpr int NT = BN / 16;

    extern __shared__ char smem[];
    const int t = threadIdx.x, lane = t & 31, wid = t >> 5;
    const int batch = blockIdx.y >> 7;
    const int m0 = (blockIdx.y & 127) * 128;
    const int n0 = blockIdx.x * BN;
    const int wm = (wid & 3) * 32;
    const int wn = (wid >> 2) * (BN / 2);

    const __nv_bfloat16* A1h = Ah.p[batch];
    const __nv_bfloat16* A1l = Al.p[batch];

    const uint32_t sbase = smem_u32(smem);
    const uint32_t a_addr0 = sbase + (uint32_t)((wm + (lane & 15)) * AW * 2 + (lane >> 4) * 16);
    const int grp = lane >> 3;
    const int b_r = (lane & 7) + ((grp >= 2) ? 8 : 0);
    const uint32_t b_addr0 = sbase + 2 * ABYTES + (uint32_t)((wn + b_r) * AW * 2 + (grp & 1) * 16);

    float acc[2][NT][4];
#pragma unroll
    for (int i = 0; i < 2; i++)
#pragma unroll
        for (int j = 0; j < NT; j++)
#pragma unroll
            for (int q = 0; q < 4; q++) acc[i][j][q] = 0.0f;

    auto load_chunk = [&](int c) {
        const int stg = c & 1;
        const int kk = c * 32;
        uint32_t base = sbase + stg * STG;
#pragma unroll
        for (int i = 0; i < 2; i++) {
            int idx = t + i * 256, r = idx >> 2, c8 = idx & 3;
            uint32_t off = (uint32_t)(r * AW * 2 + c8 * 16);
            size_t go = (size_t)(m0 + r) * Ktot + kk + c8 * 8;
            CP_ASYNC16(base + off,           A1h + go);
            CP_ASYNC16(base + ABYTES + off,  A1l + go);
        }
        uint32_t sB = base + 2 * ABYTES;
#pragma unroll
        for (int i = 0; i < BN / 64; i++) {
            int idx = t + i * 256, r = idx >> 2, c8 = idx & 3;
            uint32_t off = (uint32_t)(r * AW * 2 + c8 * 16);
            size_t go = (size_t)(n0 + r) * Ktot + kk + c8 * 8;
            CP_ASYNC16(sB + off,           Wh + go);
            CP_ASYNC16(sB + BBYTES + off,  Wl + go);
        }
        CP_COMMIT();
    };

    const int NC = Ktot >> 5;
    load_chunk(0);
    if (NC > 1) load_chunk(1);

    for (int c = 0; c < NC; c++) {
        if (c + 1 < NC) { asm volatile("cp.async.wait_group 1;" ::: "memory"); }
        else            { asm volatile("cp.async.wait_group 0;" ::: "memory"); }
        __syncthreads();

        const uint32_t aa = a_addr0 + (c & 1) * STG;
        const uint32_t bb = b_addr0 + (c & 1) * STG;
#pragma unroll
        for (int kk = 0; kk < 2; kk++) {
            uint32_t Ahf[2][4], Alf[2][4];
            LDSM4(Ahf[0], aa + kk * 32);
            LDSM4(Ahf[1], aa + 16 * AW * 2 + kk * 32);
            LDSM4(Alf[0], aa + ABYTES + kk * 32);
            LDSM4(Alf[1], aa + ABYTES + 16 * AW * 2 + kk * 32);
#pragma unroll
            for (int np = 0; np < NT / 2; np++) {
                uint32_t Bh4[4], Bl4[4];
                LDSM4(Bh4, bb + np * 16 * AW * 2 + kk * 32);
                LDSM4(Bl4, bb + BBYTES + np * 16 * AW * 2 + kk * 32);
#pragma unroll
                for (int mt = 0; mt < 2; mt++) {
                    mma_bf(acc[mt][2 * np],     Ahf[mt], Bh4[0], Bh4[1]);
                    mma_bf(acc[mt][2 * np],     Ahf[mt], Bl4[0], Bl4[1]);
                    mma_bf(acc[mt][2 * np],     Alf[mt], Bh4[0], Bh4[1]);
                    mma_bf(acc[mt][2 * np + 1], Ahf[mt], Bh4[2], Bh4[3]);
                    mma_bf(acc[mt][2 * np + 1], Ahf[mt], Bl4[2], Bl4[3]);
                    mma_bf(acc[mt][2 * np + 1], Alf[mt], Bh4[2], Bh4[3]);
                }
            }
        }
        __syncthreads();
        if (c + 2 < NC) load_chunk(c + 2);
    }

#pragma unroll
    for (int mt = 0; mt < 2; mt++) {
        int row = batch * NB + m0 + wm + mt * 16 + (lane >> 2);
#pragma unroll
        for (int nt = 0; nt < NT; nt++) {
            int col = n0 + wn + nt * 8 + (lane & 3) * 2;
            float bv0 = bias[col], bv1 = bias[col + 1];
            float x0 = acc[mt][nt][0] + bv0, x1 = acc[mt][nt][1] + bv1;
            float x2 = acc[mt][nt][2] + bv0, x3 = acc[mt][nt][3] + bv1;
            if (act) { x0 = geluf(x0); x1 = geluf(x1); x2 = geluf(x2); x3 = geluf(x3); }
            if (OUTSPLIT) {
                __nv_bfloat16* Ch = (__nv_bfloat16*)Cv;
                __nv_bfloat16* Cl = (__nv_bfloat16*)Clv;
                __nv_bfloat162 h0 = __floats2bfloat162_rn(x0, x1);
                __nv_bfloat162 h1 = __floats2bfloat162_rn(x2, x3);
                *reinterpret_cast<__nv_bfloat162*>(Ch + (size_t)row * N + col) = h0;
                *reinterpret_cast<__nv_bfloat162*>(Ch + (size_t)(row + 8) * N + col) = h1;
                *reinterpret_cast<__nv_bfloat162*>(Cl + (size_t)row * N + col) =
                    __floats2bfloat162_rn(x0 - __bfloat162float(h0.x), x1 - __bfloat162float(h0.y));
                *reinterpret_cast<__nv_bfloat162*>(Cl + (size_t)(row + 8) * N + col) =
                    __floats2bfloat162_rn(x2 - __bfloat162float(h1.x), x3 - __bfloat162float(h1.y));
            } else {
                float* C = (float*)Cv;
                *reinterpret_cast<float2*>(C + (size_t)row * N + col)       = make_float2(x0, x1);
                *reinterpret_cast<float2*>(C + (size_t)(row + 8) * N + col) = make_float2(x2, x3);
            }
        }
    }
}

// ---------- fused: rowstats + fp32->bf16 hi(/lo) conversion, one input pass ----------
__global__ void fused_stats_cvt_k(
    const float* __restrict__ f0, const float* __restrict__ f1,
    const float* __restrict__ f2, const float* __restrict__ f3,
    __nv_bfloat16* __restrict__ hi, __nv_bfloat16* __restrict__ lo,
    float* __restrict__ out)
{
    int gw = (blockIdx.x * blockDim.x + threadIdx.x) >> 5;
    int lane = threadIdx.x & 31;
    if (gw >= 4 * NB) return;
    int feat = gw >> 14;
    int m = gw & (NB - 1);
    const float* f = (feat == 0 ? f0 : feat == 1 ? f1 : feat == 2 ? f2 : f3) + (size_t)m * HD;
    __nv_bfloat16* hrow = hi + ((size_t)feat * NB + m) * HD;
    __nv_bfloat16* lrow = lo + ((size_t)feat * NB + m) * HD;

    double sum = 0.0, ssq = 0.0;
    int cnt = 0;
    for (int k = lane * 4; k < HD; k += 128) {
        float4 v = *reinterpret_cast<const float4*>(f + k);
        sum += (double)v.x + v.y + v.z + v.w;
        ssq += (double)v.x * v.x + (double)v.y * v.y + (double)v.z * v.z + (double)v.w * v.w;
        cnt += (fabsf(v.x) > 0.01f) + (fabsf(v.y) > 0.01f) + (fabsf(v.z) > 0.01f) + (fabsf(v.w) > 0.01f);
        __nv_bfloat162 h0 = __floats2bfloat162_rn(v.x, v.y);
        __nv_bfloat162 h1 = __floats2bfloat162_rn(v.z, v.w);
        reinterpret_cast<__nv_bfloat162*>(hrow + k)[0] = h0;
        reinterpret_cast<__nv_bfloat162*>(hrow + k)[1] = h1;
        if (feat < 2) {
            reinterpret_cast<__nv_bfloat162*>(lrow + k)[0] =
                __floats2bfloat162_rn(v.x - __bfloat162float(h0.x), v.y - __bfloat162float(h0.y));
            reinterpret_cast<__nv_bfloat162*>(lrow + k)[1] =
                __floats2bfloat162_rn(v.z - __bfloat162float(h1.x), v.w - __bfloat162float(h1.y));
        }
    }
#pragma unroll
    for (int o = 16; o; o >>= 1) {
        sum += __shfl_xor_sync(0xffffffffu, sum, o);
        ssq += __shfl_xor_sync(0xffffffffu, ssq, o);
        cnt += __shfl_xor_sync(0xffffffffu, cnt, o);
    }
    if (lane == 0) {
        float n = (float)sqrt(ssq);
        float nq = sigf((n - 1.0f) * 2.0f);
        float sp = cnt * (1.0f / 768.0f);
        double var = (ssq - sum * sum / 768.0) / 767.0;
        if (var < 0.0) var = 0.0;
        float sq = sigf((float)sqrt(var) * 10.0f - 1.0f);
        out[feat * NB + m] = (nq + sp + sq) * (1.0f / 3.0f);
        if (feat < 2) g_norm[feat * NB + m] = n;
    }
}

// ---------------- zero logits ----------------
__global__ void zero_k(float4* __restrict__ p, int n4) {
    int i = blockIdx.x * blockDim.x + threadIdx.x;
    if (i < n4) p[i] = make_float4(0.f, 0.f, 0.f, 0.f);
}

// ---------------- finisher: sigmoids for all heads + overall row ----------------
__global__ void finish_k(const float* __restrict__ L,
                         const float* __restrict__ b_imp, const float* __restrict__ b_disc,
                         const float* __restrict__ b_cons, const float* __restrict__ b_diff,
                         float* __restrict__ out)
{
    int i = blockIdx.x * blockDim.x + threadIdx.x;
    if (i >= NB) return;
    float bi = b_imp[0], bd = b_disc[0], bc = b_cons[0], bf = b_diff[0];
    float imp0 = sigf(L[i] + bi);
    float imp1 = sigf(L[NB + i] + bi);
    out[8 * NB + i]  = imp0;
    out[9 * NB + i]  = imp1;
    out[10 * NB + i] = sigf(L[2 * NB + i] + bi);
    out[11 * NB + i] = sigf(L[3 * NB + i] + bi);
    out[12 * NB + i] = sigf(L[4 * NB + i] + bd);
    out[13 * NB + i] = sigf(L[5 * NB + i] + bd);
    out[14 * NB + i] = sigf(L[6 * NB + i] + bd);
    out[15 * NB + i] = sigf(L[7 * NB + i] + bd);
    out[6 * NB + i]  = sigf(L[8 * NB + i] + bc);
    float cons_e     = sigf(L[9 * NB + i] + bc);
    out[7 * NB + i]  = cons_e;
    out[16 * NB + i] = sigf(L[10 * NB + i] + bf);
    float v = out[0 * NB + i] + out[1 * NB + i] + out[4 * NB + i] + out[5 * NB + i] +
              cons_e + 0.5f * (imp0 + imp1);
    out[17 * NB + i] = v * (1.0f / 6.0f);
}

// ---------------- combined transpose: 9 jobs ----------------
struct TJobs {
    const float* s[9];
    __nv_bfloat16* d[9];
    __nv_bfloat16* dl[9];
    int K[9], N[9], t0[9];
    int njobs;
};
__global__ void transpose_combo_k(TJobs J) {
    __shared__ float tile[32][33];
    int bx = blockIdx.x;
    int j = 0;
#pragma unroll
    for (int q = 1; q < 9; q++) if (q < J.njobs && bx >= J.t0[q]) j = q;
    int local = bx - J.t0[j];
    int tilesx = J.N[j] / 32;
    int txb = local % tilesx, tyb = local / tilesx;
    const float* s = J.s[j];
    int K = J.K[j], N = J.N[j];
    int n = txb * 32 + threadIdx.x;
    int k = tyb * 32 + threadIdx.y;
#pragma unroll
    for (int i = 0; i < 32; i += 8) tile[threadIdx.y + i][threadIdx.x] = s[(size_t)(k + i) * N + n];
    __syncthreads();
    int n2 = txb * 32 + threadIdx.y;
    int k2 = tyb * 32 + threadIdx.x;
    __nv_bfloat16* d = J.d[j];
    __nv_bfloat16* dl = J.dl[j];
    if (dl == nullptr) {
#pragma unroll
        for (int i = 0; i < 32; i += 8)
            d[(size_t)(n2 + i) * K + k2] = __float2bfloat16(tile[threadIdx.x][threadIdx.y + i]);
    } else {
#pragma unroll
        for (int i = 0; i < 32; i += 8) {
            float v = tile[threadIdx.x][threadIdx.y + i];
            __nv_bfloat16 h = __float2bfloat16(v);
            d[(size_t)(n2 + i) * K + k2] = h;
            dl[(size_t)(n2 + i) * K + k2] = __float2bfloat16(v - __bfloat162float(h));
        }
    }
}

// ---------------- info final (2*NB rows) ----------------
__global__ void info_final_k(const float* __restrict__ enc, float* __restrict__ outrow)
{
    int gw = (blockIdx.x * blockDim.x + threadIdx.x) >> 5;
    int lane = threadIdx.x & 31;
    if (gw >= 2 * NB) return;
    const float* e = enc + (size_t)gw * 64;
    float x0 = e[lane], x1 = e[lane + 32];
    int d0 = (int)rintf(sigf(x0) * 10.0f);
    int d1 = (int)rintf(sigf(x1) * 10.0f);
    float ent = 0.f;
#pragma unroll
    for (int b = 0; b < 11; b++) {
        int c = __popc(__ballot_sync(0xffffffffu, d0 == b)) +
                __popc(__ballot_sync(0xffffffffu, d1 == b));
        if (c > 0) {
            float p = c * (1.0f / 64.0f);
            ent -= p * logf(p + 1e-8f);
        }
    }
    if (lane == 0) {
        float eq = sigf(ent - 2.0f);
        float n = g_norm[gw];
        float cq = (n > 0.01f) ? (1.0f / 768.0f) : 0.0f;
        float t = n / fmaxf(n, 1e-12f);
        float dq = sigf(t * t - 0.5f);
        outrow[gw] = (eq + cq + dq) * (1.0f / 3.0f);
    }
}

// ---------------- host ----------------
template<int BN, int M0, int M1>
static void launch_bf2(cudaStream_t st, APtrsB A, int nb, int Khalf, int Ktot,
                       const __nv_bfloat16* Wt0, const __nv_bfloat16* Wt1,
                       int N0, int N1, const float* b0, const float* b1,
                       void* C0, void* C1, const float* w0, const float* w1, int act)
{
    int smemB = 3 * (128 + BN) * 72 * 2;
    cudaFuncSetAttribute(gemm_bf16<BN, M0, M1>,
                         cudaFuncAttributeMaxDynamicSharedMemorySize, smemB);
    dim3 g((N0 + N1) / BN, nb * 128);
    gemm_bf16<BN, M0, M1><<<g, 256, smemB, st>>>(
        A, Khalf, Ktot, Wt0, Wt1, N0, N1, b0, b1, C0, C1, w0, w1, act);
}
template<int BN, int M>
static void launch_bf(cudaStream_t st, APtrsB A, int nb, int Khalf, int Ktot,
                      const __nv_bfloat16* Wt, int N, const float* bias, void* C,
                      const float* w, int act)
{
    launch_bf2<BN, M, M>(st, A, nb, Khalf, Ktot, Wt, nullptr, N, 0, bias, nullptr,
                         C, nullptr, w, nullptr, act);
}
template<int BN, bool OUTSPLIT>
static void launch_bf3(cudaStream_t st, APtrsB Ah, APtrsB Al, int nb, int Ktot,
                       const __nv_bfloat16* Wh, const __nv_bfloat16* Wl, int N,
                       const float* bias, void* C, void* Cl, int act)
{
    int smemB = 2 * (2 * 128 * 40 * 2 + 2 * BN * 40 * 2);
    cudaFuncSetAttribute(gemm_bf3<BN, OUTSPLIT>, cudaFuncAttributeMaxDynamicSharedMemorySize, smemB);
    dim3 g(N / BN, nb * 128);
    gemm_bf3<BN, OUTSPLIT><<<g, 256, smemB, st>>>(Ah, Al, Ktot, Wh, Wl, N, bias, C, Cl, act);
}

extern "C" void kernel_launch(void* const* d_in, const int* in_sizes, int n_in,
                              void* d_out, int out_size)
{
    const float* img  = (const float*)d_in[0];
    const float* txt  = (const float*)d_in[1];
    const float* eimg = (const float*)d_in[2];
    const float* etxt = (const float*)d_in[3];
    const float* info_w1 = (const float*)d_in[5];
    const float* info_b1 = (const float*)d_in[6];
    const float* info_w2 = (const float*)d_in[7];
    const float* info_b2 = (const float*)d_in[8];
    const float* imp_w1  = (const float*)d_in[9];
    const float* imp_b1  = (const float*)d_in[10];
    const float* imp_w2  = (const float*)d_in[11];
    const float* imp_b2  = (const float*)d_in[12];
    const float* disc_w1 = (const float*)d_in[13];
    const float* disc_b1 = (const float*)d_in[14];
    const float* disc_w2 = (const float*)d_in[15];
    const float* disc_b2 = (const float*)d_in[16];
    const float* disc_w3 = (const float*)d_in[17];
    const float* disc_b3 = (const float*)d_in[18];
    const float* cons_w1 = (const float*)d_in[19];
    const float* cons_b1 = (const float*)d_in[20];
    const float* cons_w2 = (const float*)d_in[21];
    const float* cons_b2 = (const float*)d_in[22];
    const float* cons_w3 = (const float*)d_in[23];
    const float* cons_b3 = (const float*)d_in[24];
    const float* diff_w1 = (const float*)d_in[25];
    const float* diff_b1 = (const float*)d_in[26];
    const float* diff_w2 = (const float*)d_in[27];
    const float* diff_b2 = (const float*)d_in[28];
    const float* diff_w3 = (const float*)d_in[29];
    const float* diff_b3 = (const float*)d_in[30];

    float* out = (float*)d_out;

    __nv_bfloat16 *featbf, *lo1, *h2, *l2, *scrAbf, *scrAbf3, *scrCbf;
    __nv_bfloat16 *w_imp1, *w_disc1, *w_disc2, *w_cons1, *w_cons2, *w_diff1, *w_diff2;
    __nv_bfloat16 *wi1h, *wi1l, *wi2h, *wi2l;
    float *scrD2, *logit;
    cudaGetSymbolAddress((void**)&featbf, g_featbf);
    cudaGetSymbolAddress((void**)&lo1, g_lo1);
    cudaGetSymbolAddress((void**)&h2, g_h2);
    cudaGetSymbolAddress((void**)&l2, g_l2);
    cudaGetSymbolAddress((void**)&scrAbf, g_scrAbf);
    cudaGetSymbolAddress((void**)&scrAbf3, g_scrAbf3);
    cudaGetSymbolAddress((void**)&scrCbf, g_scrCbf);
    cudaGetSymbolAddress((void**)&scrD2, g_scrD2);
    cudaGetSymbolAddress((void**)&logit, g_logit);
    cudaGetSymbolAddress((void**)&w_imp1, g_w_imp1);
    cudaGetSymbolAddress((void**)&w_disc1, g_w_disc1);
    cudaGetSymbolAddress((void**)&w_disc2, g_w_disc2);
    cudaGetSymbolAddress((void**)&w_cons1, g_w_cons1);
    cudaGetSymbolAddress((void**)&w_cons2, g_w_cons2);
    cudaGetSymbolAddress((void**)&w_diff1, g_w_diff1);
    cudaGetSymbolAddress((void**)&w_diff2, g_w_diff2);
    cudaGetSymbolAddress((void**)&wi1h, g_wi1h);
    cudaGetSymbolAddress((void**)&wi1l, g_wi1l);
    cudaGetSymbolAddress((void**)&wi2h, g_wi2h);
    cudaGetSymbolAddress((void**)&wi2l, g_wi2l);

    float* logit_imp  = logit;
    float* logit_disc = logit + 4 * NB;
    float* logit_cons = logit + 8 * NB;
    float* logit_diff = logit + 10 * NB;

    const __nv_bfloat16* bimg  = featbf;
    const __nv_bfloat16* btxt  = featbf + (size_t)NB * 768;
    const __nv_bfloat16* beimg = featbf + (size_t)2 * NB * 768;
    const __nv_bfloat16* betxt = featbf + (size_t)3 * NB * 768;

    static cudaStream_t s1 = nullptr, s2 = nullptr;
    static cudaEvent_t e0 = nullptr, eF = nullptr, eW = nullptr, e1 = nullptr, e2 = nullptr;
    if (!s1) {
        cudaStreamCreateWithFlags(&s1, cudaStreamNonBlocking);
        cudaStreamCreateWithFlags(&s2, cudaStreamNonBlocking);
        cudaEventCreateWithFlags(&e0, cudaEventDisableTiming);
        cudaEventCreateWithFlags(&eF, cudaEventDisableTiming);
        cudaEventCreateWithFlags(&eW, cudaEventDisableTiming);
        cudaEventCreateWithFlags(&e1, cudaEventDisableTiming);
        cudaEventCreateWithFlags(&e2, cudaEventDisableTiming);
    }

    // fork
    cudaEventRecord(e0, 0);
    cudaStreamWaitEvent(s1, e0, 0);
    cudaStreamWaitEvent(s2, e0, 0);

    // s2: weight transposes + logit zero (weights only)
    {
        TJobs J;
        const float* srcs[9] = { imp_w1, disc_w1, disc_w2, cons_w1, cons_w2, diff_w1, diff_w2,
                                 info_w1, info_w2 };
        __nv_bfloat16* dsts[9] = { w_imp1, w_disc1, w_disc2, w_cons1, w_cons2, w_diff1, w_diff2,
                                   wi1h, wi2h };
        __nv_bfloat16* dls[9] = { nullptr, nullptr, nullptr, nullptr, nullptr, nullptr, nullptr,
                                  wi1l, wi2l };
        int Ks[9] = { 768, 768, 256, 1536, 768, 1536, 768, 768, 256 };
        int Ns[9] = { 384, 256, 64, 768, 384, 768, 384, 256, 64 };
        int tot = 0;
        for (int j = 0; j < 9; j++) {
            J.s[j] = srcs[j]; J.d[j] = dsts[j]; J.dl[j] = dls[j];
            J.K[j] = Ks[j]; J.N[j] = Ns[j];
            J.t0[j] = tot;
            tot += (Ks[j] / 32) * (Ns[j] / 32);
        }
        J.njobs = 9;
        dim3 b(32, 8);
        transpose_combo_k<<<tot, b, 0, s2>>>(J);
        zero_k<<<(11 * NB / 4 + 255) / 256, 256, 0, s2>>>((float4*)logit, 11 * NB / 4);
        cudaEventRecord(eW, s2);
    }

    // main: fused input pass (stats rows 0..3 + norms + bf16 hi/lo)
    fused_stats_cvt_k<<<(4 * NB) / 8, 256>>>(img, txt, eimg, etxt, featbf, lo1, out);
    cudaEventRecord(eF, 0);

    cudaStreamWaitEvent(0, eW, 0);
    cudaStreamWaitEvent(s1, eF, 0);
    cudaStreamWaitEvent(s1, eW, 0);
    cudaStreamWaitEvent(s2, eF, 0);

    // s1: information (rows 4,5) — bf16x3
    {
        APtrsB ah = {{ bimg, btxt, nullptr, nullptr }};
        APtrsB al = {{ lo1, lo1 + (size_t)NB * 768, nullptr, nullptr }};
        launch_bf3<128, true>(s1, ah, al, 2, 768, wi1h, wi1l, 256, info_b1, h2, l2, 1);
        APtrsB ah2 = {{ h2, h2 + (size_t)NB * 256, nullptr, nullptr }};
        APtrsB al2 = {{ l2, l2 + (size_t)NB * 256, nullptr, nullptr }};
        launch_bf3<64, false>(s1, ah2, al2, 2, 256, wi2h, wi2l, 64, info_b2, scrD2, nullptr, 0);
        info_final_k<<<(2 * NB) / 8, 256, 0, s1>>>(scrD2, out + 4 * NB);
        cudaEventRecord(e1, s1);
    }

    // main: merged imp1(head)+disc1(bf16), disc2(head), diff chain(head)
    {
        APtrsB a = {{ bimg, btxt, beimg, betxt }};
        launch_bf2<128, 2, 1>(0, a, 4, 768, 768,
                              w_imp1, w_disc1, 384, 256, imp_b1, disc_b1,
                              logit_imp, scrCbf, imp_w2, nullptr, 1);
        // disc2: batch order img,eimg,txt,etxt -> rows 12..15
        APtrsB ad2 = {{ scrCbf, scrCbf + (size_t)2 * NB * 256, scrCbf + (size_t)NB * 256,
                        scrCbf + (size_t)3 * NB * 256 }};
        launch_bf<64, 2>(0, ad2, 4, 256, 256, w_disc2, 64, disc_b2, logit_disc, disc_w3, 1);

        APtrsB af = {{ beimg, betxt, nullptr, nullptr }};
        launch_bf<128, 1>(0, af, 1, 768, 1536, w_diff1, 768, diff_b1, scrAbf3, nullptr, 1);
        APtrsB af2 = {{ scrAbf3, nullptr, nullptr, nullptr }};
        launch_bf<128, 2>(0, af2, 1, 768, 768, w_diff2, 384, diff_b2, logit_diff, diff_w3, 1);
    }

    // s2: consistency (rows 6,7), head-fused layer 2
    {
        APtrsB a = {{ bimg, btxt, beimg, betxt }};
        launch_bf<128, 1>(s2, a, 2, 768, 1536, w_cons1, 768, cons_b1, scrAbf, nullptr, 1);
        APtrsB a2 = {{ scrAbf, scrAbf + (size_t)NB * 768, nullptr, nullptr }};
        launch_bf<128, 2>(s2, a2, 2, 768, 768, w_cons2, 384, cons_b2, logit_cons, cons_w3, 1);
        cudaEventRecord(e2, s2);
    }

    // join: all logits + info rows -> one finisher (heads + overall)
    cudaStreamWaitEvent(0, e1, 0);
    cudaStreamWaitEvent(0, e2, 0);
    finish_k<<<(NB + 255) / 256, 256>>>(logit, imp_b2, disc_b3, cons_b3, diff_b3, out);
}